// round 2
// baseline (speedup 1.0000x reference)
#include <cuda_runtime.h>
#include <cstdint>

#define BB 2
#define SS 1024
#define DD 128
#define QT 64
#define NT 16   // SS/QT

// ---------------- scratch (static device globals; no allocation) ----------------
__device__ float g_Q[BB*SS*DD];
__device__ float g_K[BB*SS*DD];
__device__ float g_V[BB*SS*DD];
__device__ float g_rowK[BB*SS];
__device__ float g_segsum[BB*NT*DD];
__device__ float g_suffV[BB*SS*DD];
__device__ float g_partOut[(size_t)BB*NT*NT*QT*DD];   // 16 MB
__device__ float g_partZ[BB*NT*NT*QT];

__device__ __forceinline__ float sigmoidf_fast(float v) {
    return 1.0f / (1.0f + __expf(-v));
}

// ---------------- kernel 1: QKV = act(x @ W + b) ----------------
// grid (32 row-tiles, 3 matrices), 256 threads. 64 rows x 128 cols per block.
__global__ void qkv_kernel(const float* __restrict__ x,
                           const float* __restrict__ wq, const float* __restrict__ bq,
                           const float* __restrict__ wk, const float* __restrict__ bk,
                           const float* __restrict__ wv, const float* __restrict__ bv) {
    __shared__ float xs[64][33];
    __shared__ float ws[32][128];
    const int mat = blockIdx.y;
    const float* w    = (mat == 0) ? wq : (mat == 1) ? wk : wv;
    const float* bias = (mat == 0) ? bq : (mat == 1) ? bk : bv;
    float* out        = (mat == 0) ? g_Q : (mat == 1) ? g_K : g_V;
    const bool sig = (mat < 2);

    const int r0 = blockIdx.x * 64;
    const int tid = threadIdx.x;
    const int ty = tid >> 4, tx = tid & 15;

    float acc[4][8];
#pragma unroll
    for (int a = 0; a < 4; a++)
#pragma unroll
        for (int c = 0; c < 8; c++) acc[a][c] = 0.0f;

    for (int it = 0; it < 4; it++) {
        // load x tile 64x32
#pragma unroll
        for (int l = 0; l < 8; l++) {
            int idx = tid + l * 256;
            int r = idx >> 5, col = idx & 31;
            xs[r][col] = x[(size_t)(r0 + r) * DD + it * 32 + col];
        }
        // load w tile 32x128
#pragma unroll
        for (int l = 0; l < 16; l++) {
            int idx = tid + l * 256;
            int i = idx >> 7, j = idx & 127;
            ws[i][j] = w[(size_t)(it * 32 + i) * DD + j];
        }
        __syncthreads();
#pragma unroll
        for (int i = 0; i < 32; i++) {
            float xv[4];
#pragma unroll
            for (int a = 0; a < 4; a++) xv[a] = xs[ty * 4 + a][i];
            const float4 w0 = *(const float4*)&ws[i][tx * 8];
            const float4 w1 = *(const float4*)&ws[i][tx * 8 + 4];
#pragma unroll
            for (int a = 0; a < 4; a++) {
                acc[a][0] += xv[a] * w0.x;  acc[a][1] += xv[a] * w0.y;
                acc[a][2] += xv[a] * w0.z;  acc[a][3] += xv[a] * w0.w;
                acc[a][4] += xv[a] * w1.x;  acc[a][5] += xv[a] * w1.y;
                acc[a][6] += xv[a] * w1.z;  acc[a][7] += xv[a] * w1.w;
            }
        }
        __syncthreads();
    }
    float bv8[8];
#pragma unroll
    for (int c = 0; c < 8; c++) bv8[c] = bias[tx * 8 + c];
#pragma unroll
    for (int a = 0; a < 4; a++) {
        float v[8];
#pragma unroll
        for (int c = 0; c < 8; c++) {
            float t = acc[a][c] + bv8[c];
            v[c] = sig ? sigmoidf_fast(t) : t;
        }
        float* op = out + (size_t)(r0 + ty * 4 + a) * DD + tx * 8;
        *(float4*)op       = make_float4(v[0], v[1], v[2], v[3]);
        *(float4*)(op + 4) = make_float4(v[4], v[5], v[6], v[7]);
    }
}

// ---------------- kernel 2: row sums of K ----------------
// one warp per row. grid 256 blocks x 256 threads (8 warps -> 8 rows each).
__global__ void rowk_kernel() {
    int warp = threadIdx.x >> 5, lane = threadIdx.x & 31;
    int row = blockIdx.x * 8 + warp;
    const float4 v = *(const float4*)&g_K[(size_t)row * DD + lane * 4];
    float s = v.x + v.y + v.z + v.w;
#pragma unroll
    for (int o = 16; o > 0; o >>= 1) s += __shfl_xor_sync(0xffffffffu, s, o);
    if (lane == 0) g_rowK[row] = s;
}

// ---------------- kernel 3: per-segment V sums (64-row segments) ----------------
__global__ void segsum_kernel() {
    int b = blockIdx.x >> 4, seg = blockIdx.x & 15, d = threadIdx.x;
    float s = 0.0f;
    const float* vp = g_V + ((size_t)b * SS + seg * 64) * DD + d;
#pragma unroll 8
    for (int i = 0; i < 64; i++) s += vp[(size_t)i * DD];
    g_segsum[(b * NT + seg) * DD + d] = s;
}

// ---------------- kernel 4: suffix sums of V ----------------
__global__ void suffix_kernel() {
    int b = blockIdx.x >> 4, seg = blockIdx.x & 15, d = threadIdx.x;
    float acc = 0.0f;
    for (int sg = seg + 1; sg < NT; sg++) acc += g_segsum[(b * NT + sg) * DD + d];
    for (int i = 63; i >= 0; i--) {
        int s = seg * 64 + i;
        size_t off = ((size_t)b * SS + s) * DD + d;
        g_suffV[off] = acc;
        acc += g_V[off];
    }
}

// ---------------- kernel 5: main fused truth + exp + partial (w @ V) ----------------
// grid (kt=16, qt=16, b=2), 256 threads, dynamic smem.
#define QS_STR 129
#define WS_STR 68
#define SMEM_MAIN ((64*QS_STR*2 + 64*DD + 64*WS_STR + 64) * 4)

__global__ void main_kernel(float* __restrict__ truth) {
    extern __shared__ float sm[];
    float* Qs    = sm;                    // [64][129]
    float* Ks    = Qs + 64 * QS_STR;      // [64][129]
    float* Vs    = Ks + 64 * QS_STR;      // [64][128]
    float* Ws    = Vs + 64 * DD;          // [64][68]
    float* rowKs = Ws + 64 * WS_STR;      // [64]

    const int kt = blockIdx.x, qt = blockIdx.y, b = blockIdx.z;
    const int tid = threadIdx.x;
    const int qb = qt * QT, kb = kt * QT;

    if (kt > qt) {   // strictly-upper tile: zero-fill truth and exit
        int r = tid >> 4, c4 = tid & 15;
        float4 z = make_float4(0.f, 0.f, 0.f, 0.f);
#pragma unroll
        for (int rr = 0; rr < 4; rr++) {
            int row = r + rr * 16;
            *(float4*)&truth[((size_t)(b * SS + qb + row)) * SS + kb + c4 * 4] = z;
        }
        return;
    }

    {   // stage tiles
        const float* Qg = g_Q + ((size_t)b * SS + qb) * DD;
        const float* Kg = g_K + ((size_t)b * SS + kb) * DD;
        const float* Vg = g_V + ((size_t)b * SS + kb) * DD;
#pragma unroll
        for (int l = 0; l < 32; l++) {
            int idx = tid + l * 256;
            int r = idx >> 7, dd = idx & 127;
            Qs[r * QS_STR + dd] = Qg[idx];
            Ks[r * QS_STR + dd] = Kg[idx];
            Vs[idx] = Vg[idx];
        }
        if (tid < 64) rowKs[tid] = g_rowK[b * SS + kb + tid];
    }
    __syncthreads();

    const int ty = tid >> 4, tx = tid & 15;
    const float* qp = Qs + (ty * 4) * QS_STR;
    const float* kp = Ks + (tx * 4) * QS_STR;

    float acc[4][4];
#pragma unroll
    for (int a = 0; a < 4; a++)
#pragma unroll
        for (int j = 0; j < 4; j++) acc[a][j] = 0.0f;

#pragma unroll 8
    for (int dd = 0; dd < DD; dd++) {
        float qv[4], kv[4], cv[4];
#pragma unroll
        for (int a = 0; a < 4; a++) qv[a] = qp[a * QS_STR + dd];
#pragma unroll
        for (int j = 0; j < 4; j++) { kv[j] = kp[j * QS_STR + dd]; cv[j] = 1.0f - kv[j]; }
#pragma unroll
        for (int a = 0; a < 4; a++)
#pragma unroll
            for (int j = 0; j < 4; j++)
                if (qv[a] <= kv[j]) acc[a][j] += cv[j];
    }

    // truth values + softmax weights
    float wv_[4][4];
#pragma unroll
    for (int a = 0; a < 4; a++) {
        int qg = qb + ty * 4 + a;
#pragma unroll
        for (int j = 0; j < 4; j++) {
            int kg = kb + tx * 4 + j;
            float t = (rowKs[tx * 4 + j] + acc[a][j]) * (1.0f / DD);
            bool valid = (kg <= qg);
            t = valid ? t : 0.0f;
            Ws[(ty * 4 + a) * WS_STR + tx * 4 + j] = t;
            wv_[a][j] = valid ? __expf(10.0f * t) : 0.0f;
        }
    }
    __syncthreads();

    {   // coalesced truth store
        int r = tid >> 4, c4 = tid & 15;
#pragma unroll
        for (int rr = 0; rr < 4; rr++) {
            int row = r + rr * 16;
            float4 tv = *(float4*)&Ws[row * WS_STR + c4 * 4];
            *(float4*)&truth[((size_t)(b * SS + qb + row)) * SS + kb + c4 * 4] = tv;
        }
    }
    __syncthreads();

    // overwrite Ws with weights
#pragma unroll
    for (int a = 0; a < 4; a++)
#pragma unroll
        for (int j = 0; j < 4; j++)
            Ws[(ty * 4 + a) * WS_STR + tx * 4 + j] = wv_[a][j];

    // partial Z per q-row: reduce across the 16 tx lanes (lane bits 0-3)
    const int slot = (b * NT + qt) * NT + kt;
    {
        float rs[4];
#pragma unroll
        for (int a = 0; a < 4; a++)
            rs[a] = wv_[a][0] + wv_[a][1] + wv_[a][2] + wv_[a][3];
#pragma unroll
        for (int a = 0; a < 4; a++) {
            rs[a] += __shfl_xor_sync(0xffffffffu, rs[a], 8);
            rs[a] += __shfl_xor_sync(0xffffffffu, rs[a], 4);
            rs[a] += __shfl_xor_sync(0xffffffffu, rs[a], 2);
            rs[a] += __shfl_xor_sync(0xffffffffu, rs[a], 1);
        }
        if (tx == 0) {
#pragma unroll
            for (int a = 0; a < 4; a++)
                g_partZ[(size_t)slot * QT + ty * 4 + a] = rs[a];
        }
    }
    __syncthreads();

    // partial out = W(64x64) @ V(64x128); thread tile 4q x 8d
    float oacc[4][8];
#pragma unroll
    for (int a = 0; a < 4; a++)
#pragma unroll
        for (int c = 0; c < 8; c++) oacc[a][c] = 0.0f;

#pragma unroll 4
    for (int kk = 0; kk < QT; kk++) {
        float wr[4];
#pragma unroll
        for (int a = 0; a < 4; a++) wr[a] = Ws[(ty * 4 + a) * WS_STR + kk];
        const float4 va = *(const float4*)&Vs[kk * DD + tx * 8];
        const float4 vb = *(const float4*)&Vs[kk * DD + tx * 8 + 4];
#pragma unroll
        for (int a = 0; a < 4; a++) {
            oacc[a][0] += wr[a] * va.x;  oacc[a][1] += wr[a] * va.y;
            oacc[a][2] += wr[a] * va.z;  oacc[a][3] += wr[a] * va.w;
            oacc[a][4] += wr[a] * vb.x;  oacc[a][5] += wr[a] * vb.y;
            oacc[a][6] += wr[a] * vb.z;  oacc[a][7] += wr[a] * vb.w;
        }
    }
    float* po = g_partOut + (size_t)slot * QT * DD;
#pragma unroll
    for (int a = 0; a < 4; a++) {
        *(float4*)&po[(ty * 4 + a) * DD + tx * 8] =
            make_float4(oacc[a][0], oacc[a][1], oacc[a][2], oacc[a][3]);
        *(float4*)&po[(ty * 4 + a) * DD + tx * 8 + 4] =
            make_float4(oacc[a][4], oacc[a][5], oacc[a][6], oacc[a][7]);
    }
}

// ---------------- kernel 6: combine partials + masked tail, normalize ----------------
// grid (qt=16, b=2), 256 threads
__global__ void combine_kernel(float* __restrict__ out) {
    const int qt = blockIdx.x, b = blockIdx.y;
    const int tid = threadIdx.x;
    const int ty = tid >> 4, tx = tid & 15;

    float acc[4][8];
    float z[4];
#pragma unroll
    for (int a = 0; a < 4; a++) {
        z[a] = 0.0f;
#pragma unroll
        for (int c = 0; c < 8; c++) acc[a][c] = 0.0f;
    }

    for (int kt = 0; kt <= qt; kt++) {
        int slot = (b * NT + qt) * NT + kt;
        const float* po = g_partOut + (size_t)slot * QT * DD;
#pragma unroll
        for (int a = 0; a < 4; a++) {
            const float4 v0 = *(const float4*)&po[(ty * 4 + a) * DD + tx * 8];
            const float4 v1 = *(const float4*)&po[(ty * 4 + a) * DD + tx * 8 + 4];
            acc[a][0] += v0.x; acc[a][1] += v0.y; acc[a][2] += v0.z; acc[a][3] += v0.w;
            acc[a][4] += v1.x; acc[a][5] += v1.y; acc[a][6] += v1.z; acc[a][7] += v1.w;
            z[a] += g_partZ[(size_t)slot * QT + ty * 4 + a];
        }
    }
#pragma unroll
    for (int a = 0; a < 4; a++) {
        int qg = qt * QT + ty * 4 + a;
        float Z = z[a] + (float)(SS - 1 - qg);
        float r = 1.0f / Z;
        const float* sv = g_suffV + ((size_t)b * SS + qg) * DD + tx * 8;
        const float4 s0 = *(const float4*)sv;
        const float4 s1 = *(const float4*)(sv + 4);
        float4 o0, o1;
        o0.x = (acc[a][0] + s0.x) * r;  o0.y = (acc[a][1] + s0.y) * r;
        o0.z = (acc[a][2] + s0.z) * r;  o0.w = (acc[a][3] + s0.w) * r;
        o1.x = (acc[a][4] + s1.x) * r;  o1.y = (acc[a][5] + s1.y) * r;
        o1.z = (acc[a][6] + s1.z) * r;  o1.w = (acc[a][7] + s1.w) * r;
        float* op = out + ((size_t)b * SS + qg) * DD + tx * 8;
        *(float4*)op       = o0;
        *(float4*)(op + 4) = o1;
    }
}

// ---------------- launch ----------------
extern "C" void kernel_launch(void* const* d_in, const int* in_sizes, int n_in,
                              void* d_out, int out_size) {
    const float* x  = (const float*)d_in[0];
    const float* wq = (const float*)d_in[1];
    const float* bq = (const float*)d_in[2];
    const float* wk = (const float*)d_in[3];
    const float* bk = (const float*)d_in[4];
    const float* wv = (const float*)d_in[5];
    const float* bv = (const float*)d_in[6];
    float* out = (float*)d_out;
    float* truth = out + (size_t)BB * SS * DD;   // output first, then attention_truth

    static int smem_set = 0;
    (void)smem_set;
    cudaFuncSetAttribute(main_kernel, cudaFuncAttributeMaxDynamicSharedMemorySize, SMEM_MAIN);

    qkv_kernel<<<dim3(32, 3), 256>>>(x, wq, bq, wk, bk, wv, bv);
    rowk_kernel<<<256, 256>>>();
    segsum_kernel<<<BB * NT, 128>>>();
    suffix_kernel<<<BB * NT, 128>>>();
    main_kernel<<<dim3(NT, NT, BB), 256, SMEM_MAIN>>>(truth);
    combine_kernel<<<dim3(NT, BB), 256>>>(out);
}

// round 3
// speedup vs baseline: 1.2102x; 1.2102x over previous
#include <cuda_runtime.h>
#include <cstdint>

#define BB 2
#define SS 1024
#define DD 128
#define QT 64
#define NT 16   // SS/QT

// ---------------- scratch (static device globals; no allocation) ----------------
__device__ float g_Q[BB*SS*DD];
__device__ float g_K[BB*SS*DD];
__device__ float g_V[BB*SS*DD];
__device__ float g_rowK[BB*SS];
__device__ float g_segsum[BB*NT*DD];
__device__ float g_suffV[BB*SS*DD];
__device__ float g_partOut[(size_t)BB*NT*NT*QT*DD];   // 16 MB
__device__ float g_partZ[BB*NT*NT*QT];

__device__ __forceinline__ float sigmoidf_fast(float v) {
    return 1.0f / (1.0f + __expf(-v));
}

// ---------------- kernel 1: QKV = act(x @ W + b), fused rowK / segsum epilogues ----
// grid (32 row-tiles, 3 matrices), 256 threads. 64 rows x 128 cols per block.
// mat==1 (K): also writes g_rowK[row] = sum_d sigmoid(K)
// mat==2 (V): also writes g_segsum[seg][d] = sum over the block's 64 rows of V
__global__ void qkv_kernel(const float* __restrict__ x,
                           const float* __restrict__ wq, const float* __restrict__ bq,
                           const float* __restrict__ wk, const float* __restrict__ bk,
                           const float* __restrict__ wv, const float* __restrict__ bv) {
    __shared__ float xs[64][33];
    __shared__ float ws[32][128];
    const int mat = blockIdx.y;
    const float* w    = (mat == 0) ? wq : (mat == 1) ? wk : wv;
    const float* bias = (mat == 0) ? bq : (mat == 1) ? bk : bv;
    float* out        = (mat == 0) ? g_Q : (mat == 1) ? g_K : g_V;
    const bool sig = (mat < 2);

    const int r0 = blockIdx.x * 64;
    const int tid = threadIdx.x;
    const int ty = tid >> 4, tx = tid & 15;

    float acc[4][8];
#pragma unroll
    for (int a = 0; a < 4; a++)
#pragma unroll
        for (int c = 0; c < 8; c++) acc[a][c] = 0.0f;

    for (int it = 0; it < 4; it++) {
        // load x tile 64x32
#pragma unroll
        for (int l = 0; l < 8; l++) {
            int idx = tid + l * 256;
            int r = idx >> 5, col = idx & 31;
            xs[r][col] = x[(size_t)(r0 + r) * DD + it * 32 + col];
        }
        // load w tile 32x128
#pragma unroll
        for (int l = 0; l < 16; l++) {
            int idx = tid + l * 256;
            int i = idx >> 7, j = idx & 127;
            ws[i][j] = w[(size_t)(it * 32 + i) * DD + j];
        }
        __syncthreads();
#pragma unroll
        for (int i = 0; i < 32; i++) {
            float xv[4];
#pragma unroll
            for (int a = 0; a < 4; a++) xv[a] = xs[ty * 4 + a][i];
            const float4 w0 = *(const float4*)&ws[i][tx * 8];
            const float4 w1 = *(const float4*)&ws[i][tx * 8 + 4];
#pragma unroll
            for (int a = 0; a < 4; a++) {
                acc[a][0] += xv[a] * w0.x;  acc[a][1] += xv[a] * w0.y;
                acc[a][2] += xv[a] * w0.z;  acc[a][3] += xv[a] * w0.w;
                acc[a][4] += xv[a] * w1.x;  acc[a][5] += xv[a] * w1.y;
                acc[a][6] += xv[a] * w1.z;  acc[a][7] += xv[a] * w1.w;
            }
        }
        __syncthreads();
    }
    float bv8[8];
#pragma unroll
    for (int c = 0; c < 8; c++) bv8[c] = bias[tx * 8 + c];

    float colpart[8];
#pragma unroll
    for (int c = 0; c < 8; c++) colpart[c] = 0.0f;

#pragma unroll
    for (int a = 0; a < 4; a++) {
        float v[8];
#pragma unroll
        for (int c = 0; c < 8; c++) {
            float t = acc[a][c] + bv8[c];
            v[c] = sig ? sigmoidf_fast(t) : t;
        }
        float* op = out + (size_t)(r0 + ty * 4 + a) * DD + tx * 8;
        *(float4*)op       = make_float4(v[0], v[1], v[2], v[3]);
        *(float4*)(op + 4) = make_float4(v[4], v[5], v[6], v[7]);

        if (mat == 1) {
            // row sum of sigmoid(K): reduce 8 cols locally, then across the 16 tx lanes
            float rs = ((v[0] + v[1]) + (v[2] + v[3])) + ((v[4] + v[5]) + (v[6] + v[7]));
            rs += __shfl_xor_sync(0xffffffffu, rs, 1);
            rs += __shfl_xor_sync(0xffffffffu, rs, 2);
            rs += __shfl_xor_sync(0xffffffffu, rs, 4);
            rs += __shfl_xor_sync(0xffffffffu, rs, 8);
            if (tx == 0) g_rowK[r0 + ty * 4 + a] = rs;
        } else if (mat == 2) {
#pragma unroll
            for (int c = 0; c < 8; c++) colpart[c] += v[c];
        }
    }

    if (mat == 2) {
        // column sums over this block's 64 rows -> g_segsum[blockIdx.x][:]
        __syncthreads();   // ws no longer needed by GEMM loop
#pragma unroll
        for (int c = 0; c < 8; c++) ws[ty][tx * 8 + c] = colpart[c];
        __syncthreads();
        if (tid < 128) {
            float s = 0.0f;
#pragma unroll
            for (int t = 0; t < 16; t++) s += ws[t][tid];
            g_segsum[blockIdx.x * DD + tid] = s;
        }
    }
}

// ---------------- kernel 2: suffix sums of V (MLP-friendly) ----------------
// grid BB*NT blocks, 128 threads (one per d). Batch rows in groups of 8 so the
// gmem loads are independent (MLP=8) and the serial chain is FADD-only.
__global__ void suffix_kernel() {
    const int b = blockIdx.x >> 4, seg = blockIdx.x & 15, d = threadIdx.x;

    // tail = sum of later segments (predicated full unroll -> MLP up to 15)
    float acc = 0.0f;
#pragma unroll
    for (int sg = 0; sg < NT; sg++) {
        float v = (sg > seg) ? g_segsum[(b * NT + sg) * DD + d] : 0.0f;
        acc += v;
    }

    const float* vbase = g_V    + ((size_t)b * SS + seg * 64) * DD + d;
    float*       sbase = g_suffV + ((size_t)b * SS + seg * 64) * DD + d;

#pragma unroll
    for (int i0 = 56; i0 >= 0; i0 -= 8) {
        float v[8];
#pragma unroll
        for (int j = 0; j < 8; j++) v[j] = vbase[(size_t)(i0 + j) * DD];
#pragma unroll
        for (int j = 7; j >= 0; j--) {
            sbase[(size_t)(i0 + j) * DD] = acc;
            acc += v[j];
        }
    }
}

// ---------------- kernel 3: main fused truth + exp + partial (w @ V) ----------------
// grid (kt=16, qt=16, b=2), 256 threads, dynamic smem.
#define QS_STR 129
#define WS_STR 68
#define SMEM_MAIN ((64*QS_STR*2 + 64*DD + 64*WS_STR + 64) * 4)

__global__ void main_kernel(float* __restrict__ truth) {
    extern __shared__ float sm[];
    float* Qs    = sm;                    // [64][129]
    float* Ks    = Qs + 64 * QS_STR;      // [64][129]
    float* Vs    = Ks + 64 * QS_STR;      // [64][128]
    float* Ws    = Vs + 64 * DD;          // [64][68]
    float* rowKs = Ws + 64 * WS_STR;      // [64]

    const int kt = blockIdx.x, qt = blockIdx.y, b = blockIdx.z;
    const int tid = threadIdx.x;
    const int qb = qt * QT, kb = kt * QT;

    if (kt > qt) {   // strictly-upper tile: zero-fill truth and exit
        int r = tid >> 4, c4 = tid & 15;
        float4 z = make_float4(0.f, 0.f, 0.f, 0.f);
#pragma unroll
        for (int rr = 0; rr < 4; rr++) {
            int row = r + rr * 16;
            *(float4*)&truth[((size_t)(b * SS + qb + row)) * SS + kb + c4 * 4] = z;
        }
        return;
    }

    {   // stage tiles
        const float* Qg = g_Q + ((size_t)b * SS + qb) * DD;
        const float* Kg = g_K + ((size_t)b * SS + kb) * DD;
        const float* Vg = g_V + ((size_t)b * SS + kb) * DD;
#pragma unroll
        for (int l = 0; l < 32; l++) {
            int idx = tid + l * 256;
            int r = idx >> 7, dd = idx & 127;
            Qs[r * QS_STR + dd] = Qg[idx];
            Ks[r * QS_STR + dd] = Kg[idx];
            Vs[idx] = Vg[idx];
        }
        if (tid < 64) rowKs[tid] = g_rowK[b * SS + kb + tid];
    }
    __syncthreads();

    const int ty = tid >> 4, tx = tid & 15;
    const float* qp = Qs + (ty * 4) * QS_STR;
    const float* kp = Ks + (tx * 4) * QS_STR;

    float acc[4][4];
#pragma unroll
    for (int a = 0; a < 4; a++)
#pragma unroll
        for (int j = 0; j < 4; j++) acc[a][j] = 0.0f;

#pragma unroll 8
    for (int dd = 0; dd < DD; dd++) {
        float qv[4], kv[4], cv[4];
#pragma unroll
        for (int a = 0; a < 4; a++) qv[a] = qp[a * QS_STR + dd];
#pragma unroll
        for (int j = 0; j < 4; j++) { kv[j] = kp[j * QS_STR + dd]; cv[j] = 1.0f - kv[j]; }
#pragma unroll
        for (int a = 0; a < 4; a++)
#pragma unroll
            for (int j = 0; j < 4; j++)
                if (qv[a] <= kv[j]) acc[a][j] += cv[j];
    }

    // truth values + softmax weights
    float wv_[4][4];
#pragma unroll
    for (int a = 0; a < 4; a++) {
        int qg = qb + ty * 4 + a;
#pragma unroll
        for (int j = 0; j < 4; j++) {
            int kg = kb + tx * 4 + j;
            float t = (rowKs[tx * 4 + j] + acc[a][j]) * (1.0f / DD);
            bool valid = (kg <= qg);
            t = valid ? t : 0.0f;
            Ws[(ty * 4 + a) * WS_STR + tx * 4 + j] = t;
            wv_[a][j] = valid ? __expf(10.0f * t) : 0.0f;
        }
    }
    __syncthreads();

    {   // coalesced truth store
        int r = tid >> 4, c4 = tid & 15;
#pragma unroll
        for (int rr = 0; rr < 4; rr++) {
            int row = r + rr * 16;
            float4 tv = *(float4*)&Ws[row * WS_STR + c4 * 4];
            *(float4*)&truth[((size_t)(b * SS + qb + row)) * SS + kb + c4 * 4] = tv;
        }
    }
    __syncthreads();

    // overwrite Ws with weights
#pragma unroll
    for (int a = 0; a < 4; a++)
#pragma unroll
        for (int j = 0; j < 4; j++)
            Ws[(ty * 4 + a) * WS_STR + tx * 4 + j] = wv_[a][j];

    // partial Z per q-row: reduce across the 16 tx lanes (lane bits 0-3)
    const int slot = (b * NT + qt) * NT + kt;
    {
        float rs[4];
#pragma unroll
        for (int a = 0; a < 4; a++)
            rs[a] = wv_[a][0] + wv_[a][1] + wv_[a][2] + wv_[a][3];
#pragma unroll
        for (int a = 0; a < 4; a++) {
            rs[a] += __shfl_xor_sync(0xffffffffu, rs[a], 8);
            rs[a] += __shfl_xor_sync(0xffffffffu, rs[a], 4);
            rs[a] += __shfl_xor_sync(0xffffffffu, rs[a], 2);
            rs[a] += __shfl_xor_sync(0xffffffffu, rs[a], 1);
        }
        if (tx == 0) {
#pragma unroll
            for (int a = 0; a < 4; a++)
                g_partZ[(size_t)slot * QT + ty * 4 + a] = rs[a];
        }
    }
    __syncthreads();

    // partial out = W(64x64) @ V(64x128); thread tile 4q x 8d
    float oacc[4][8];
#pragma unroll
    for (int a = 0; a < 4; a++)
#pragma unroll
        for (int c = 0; c < 8; c++) oacc[a][c] = 0.0f;

#pragma unroll 4
    for (int kk = 0; kk < QT; kk++) {
        float wr[4];
#pragma unroll
        for (int a = 0; a < 4; a++) wr[a] = Ws[(ty * 4 + a) * WS_STR + kk];
        const float4 va = *(const float4*)&Vs[kk * DD + tx * 8];
        const float4 vb = *(const float4*)&Vs[kk * DD + tx * 8 + 4];
#pragma unroll
        for (int a = 0; a < 4; a++) {
            oacc[a][0] += wr[a] * va.x;  oacc[a][1] += wr[a] * va.y;
            oacc[a][2] += wr[a] * va.z;  oacc[a][3] += wr[a] * va.w;
            oacc[a][4] += wr[a] * vb.x;  oacc[a][5] += wr[a] * vb.y;
            oacc[a][6] += wr[a] * vb.z;  oacc[a][7] += wr[a] * vb.w;
        }
    }
    float* po = g_partOut + (size_t)slot * QT * DD;
#pragma unroll
    for (int a = 0; a < 4; a++) {
        *(float4*)&po[(ty * 4 + a) * DD + tx * 8] =
            make_float4(oacc[a][0], oacc[a][1], oacc[a][2], oacc[a][3]);
        *(float4*)&po[(ty * 4 + a) * DD + tx * 8 + 4] =
            make_float4(oacc[a][4], oacc[a][5], oacc[a][6], oacc[a][7]);
    }
}

// ---------------- kernel 4: combine partials + masked tail, normalize ----------------
// grid (qt=16, b=2), 256 threads
__global__ void combine_kernel(float* __restrict__ out) {
    const int qt = blockIdx.x, b = blockIdx.y;
    const int tid = threadIdx.x;
    const int ty = tid >> 4, tx = tid & 15;

    float acc[4][8];
    float z[4];
#pragma unroll
    for (int a = 0; a < 4; a++) {
        z[a] = 0.0f;
#pragma unroll
        for (int c = 0; c < 8; c++) acc[a][c] = 0.0f;
    }

    for (int kt = 0; kt <= qt; kt++) {
        int slot = (b * NT + qt) * NT + kt;
        const float* po = g_partOut + (size_t)slot * QT * DD;
#pragma unroll
        for (int a = 0; a < 4; a++) {
            const float4 v0 = *(const float4*)&po[(ty * 4 + a) * DD + tx * 8];
            const float4 v1 = *(const float4*)&po[(ty * 4 + a) * DD + tx * 8 + 4];
            acc[a][0] += v0.x; acc[a][1] += v0.y; acc[a][2] += v0.z; acc[a][3] += v0.w;
            acc[a][4] += v1.x; acc[a][5] += v1.y; acc[a][6] += v1.z; acc[a][7] += v1.w;
            z[a] += g_partZ[(size_t)slot * QT + ty * 4 + a];
        }
    }
#pragma unroll
    for (int a = 0; a < 4; a++) {
        int qg = qt * QT + ty * 4 + a;
        float Z = z[a] + (float)(SS - 1 - qg);
        float r = 1.0f / Z;
        const float* sv = g_suffV + ((size_t)b * SS + qg) * DD + tx * 8;
        const float4 s0 = *(const float4*)sv;
        const float4 s1 = *(const float4*)(sv + 4);
        float4 o0, o1;
        o0.x = (acc[a][0] + s0.x) * r;  o0.y = (acc[a][1] + s0.y) * r;
        o0.z = (acc[a][2] + s0.z) * r;  o0.w = (acc[a][3] + s0.w) * r;
        o1.x = (acc[a][4] + s1.x) * r;  o1.y = (acc[a][5] + s1.y) * r;
        o1.z = (acc[a][6] + s1.z) * r;  o1.w = (acc[a][7] + s1.w) * r;
        float* op = out + ((size_t)b * SS + qg) * DD + tx * 8;
        *(float4*)op       = o0;
        *(float4*)(op + 4) = o1;
    }
}

// ---------------- launch ----------------
extern "C" void kernel_launch(void* const* d_in, const int* in_sizes, int n_in,
                              void* d_out, int out_size) {
    const float* x  = (const float*)d_in[0];
    const float* wq = (const float*)d_in[1];
    const float* bq = (const float*)d_in[2];
    const float* wk = (const float*)d_in[3];
    const float* bk = (const float*)d_in[4];
    const float* wv = (const float*)d_in[5];
    const float* bv = (const float*)d_in[6];
    float* out = (float*)d_out;
    float* truth = out + (size_t)BB * SS * DD;   // output first, then attention_truth

    cudaFuncSetAttribute(main_kernel, cudaFuncAttributeMaxDynamicSharedMemorySize, SMEM_MAIN);

    qkv_kernel<<<dim3(32, 3), 256>>>(x, wq, bq, wk, bk, wv, bv);
    suffix_kernel<<<BB * NT, 128>>>();
    main_kernel<<<dim3(NT, NT, BB), 256, SMEM_MAIN>>>(truth);
    combine_kernel<<<dim3(NT, BB), 256>>>(out);
}

// round 4
// speedup vs baseline: 1.4257x; 1.1781x over previous
#include <cuda_runtime.h>
#include <cstdint>

#define BB 2
#define SS 1024
#define DD 128
#define QT 64
#define NT 16   // SS/QT

// ---------------- scratch (static device globals; no allocation) ----------------
__device__ float g_Q[BB*SS*DD];
__device__ float g_K[BB*SS*DD];
__device__ float g_V[BB*SS*DD];
__device__ float g_rowK[BB*SS];
__device__ float g_segsum[BB*NT*DD];
__device__ float g_suffV[BB*SS*DD];
__device__ float g_partOut[(size_t)BB*NT*NT*QT*DD];   // 16 MB
__device__ float g_partZ[BB*NT*NT*QT];

__device__ __forceinline__ float sigmoidf_fast(float v) {
    return 1.0f / (1.0f + __expf(-v));
}

// ---------------- kernel 1: QKV = act(x @ W + b), fused rowK / segsum epilogues ----
__global__ void qkv_kernel(const float* __restrict__ x,
                           const float* __restrict__ wq, const float* __restrict__ bq,
                           const float* __restrict__ wk, const float* __restrict__ bk,
                           const float* __restrict__ wv, const float* __restrict__ bv) {
    __shared__ float xs[64][33];
    __shared__ float ws[32][128];
    const int mat = blockIdx.y;
    const float* w    = (mat == 0) ? wq : (mat == 1) ? wk : wv;
    const float* bias = (mat == 0) ? bq : (mat == 1) ? bk : bv;
    float* out        = (mat == 0) ? g_Q : (mat == 1) ? g_K : g_V;
    const bool sig = (mat < 2);

    const int r0 = blockIdx.x * 64;
    const int tid = threadIdx.x;
    const int ty = tid >> 4, tx = tid & 15;

    float acc[4][8];
#pragma unroll
    for (int a = 0; a < 4; a++)
#pragma unroll
        for (int c = 0; c < 8; c++) acc[a][c] = 0.0f;

    for (int it = 0; it < 4; it++) {
#pragma unroll
        for (int l = 0; l < 8; l++) {
            int idx = tid + l * 256;
            int r = idx >> 5, col = idx & 31;
            xs[r][col] = x[(size_t)(r0 + r) * DD + it * 32 + col];
        }
#pragma unroll
        for (int l = 0; l < 16; l++) {
            int idx = tid + l * 256;
            int i = idx >> 7, j = idx & 127;
            ws[i][j] = w[(size_t)(it * 32 + i) * DD + j];
        }
        __syncthreads();
#pragma unroll
        for (int i = 0; i < 32; i++) {
            float xv[4];
#pragma unroll
            for (int a = 0; a < 4; a++) xv[a] = xs[ty * 4 + a][i];
            const float4 w0 = *(const float4*)&ws[i][tx * 8];
            const float4 w1 = *(const float4*)&ws[i][tx * 8 + 4];
#pragma unroll
            for (int a = 0; a < 4; a++) {
                acc[a][0] += xv[a] * w0.x;  acc[a][1] += xv[a] * w0.y;
                acc[a][2] += xv[a] * w0.z;  acc[a][3] += xv[a] * w0.w;
                acc[a][4] += xv[a] * w1.x;  acc[a][5] += xv[a] * w1.y;
                acc[a][6] += xv[a] * w1.z;  acc[a][7] += xv[a] * w1.w;
            }
        }
        __syncthreads();
    }
    float bv8[8];
#pragma unroll
    for (int c = 0; c < 8; c++) bv8[c] = bias[tx * 8 + c];

    float colpart[8];
#pragma unroll
    for (int c = 0; c < 8; c++) colpart[c] = 0.0f;

#pragma unroll
    for (int a = 0; a < 4; a++) {
        float v[8];
#pragma unroll
        for (int c = 0; c < 8; c++) {
            float t = acc[a][c] + bv8[c];
            v[c] = sig ? sigmoidf_fast(t) : t;
        }
        float* op = out + (size_t)(r0 + ty * 4 + a) * DD + tx * 8;
        *(float4*)op       = make_float4(v[0], v[1], v[2], v[3]);
        *(float4*)(op + 4) = make_float4(v[4], v[5], v[6], v[7]);

        if (mat == 1) {
            float rs = ((v[0] + v[1]) + (v[2] + v[3])) + ((v[4] + v[5]) + (v[6] + v[7]));
            rs += __shfl_xor_sync(0xffffffffu, rs, 1);
            rs += __shfl_xor_sync(0xffffffffu, rs, 2);
            rs += __shfl_xor_sync(0xffffffffu, rs, 4);
            rs += __shfl_xor_sync(0xffffffffu, rs, 8);
            if (tx == 0) g_rowK[r0 + ty * 4 + a] = rs;
        } else if (mat == 2) {
#pragma unroll
            for (int c = 0; c < 8; c++) colpart[c] += v[c];
        }
    }

    if (mat == 2) {
        __syncthreads();
#pragma unroll
        for (int c = 0; c < 8; c++) ws[ty][tx * 8 + c] = colpart[c];
        __syncthreads();
        if (tid < 128) {
            float s = 0.0f;
#pragma unroll
            for (int t = 0; t < 16; t++) s += ws[t][tid];
            g_segsum[blockIdx.x * DD + tid] = s;
        }
    }
}

// ---------------- kernel 2: suffix sums of V (MLP-friendly) ----------------
__global__ void suffix_kernel() {
    const int b = blockIdx.x >> 4, seg = blockIdx.x & 15, d = threadIdx.x;

    float acc = 0.0f;
#pragma unroll
    for (int sg = 0; sg < NT; sg++) {
        float v = (sg > seg) ? g_segsum[(b * NT + sg) * DD + d] : 0.0f;
        acc += v;
    }

    const float* vbase = g_V    + ((size_t)b * SS + seg * 64) * DD + d;
    float*       sbase = g_suffV + ((size_t)b * SS + seg * 64) * DD + d;

#pragma unroll
    for (int i0 = 56; i0 >= 0; i0 -= 8) {
        float v[8];
#pragma unroll
        for (int j = 0; j < 8; j++) v[j] = vbase[(size_t)(i0 + j) * DD];
#pragma unroll
        for (int j = 7; j >= 0; j--) {
            sbase[(size_t)(i0 + j) * DD] = acc;
            acc += v[j];
        }
    }
}

// ---------------- kernel 3: main fused truth + exp + partial (w @ V) ----------------
// grid (kt=16, qt=16, b=2), 256 threads. smem 84KB -> 2 CTAs/SM (one wave).
// V is staged into the Q buffer AFTER the truth phase (Q no longer needed).
#define QS_STR 129
#define WS_STR 68
#define SMEM_MAIN ((64*QS_STR*2 + 64*WS_STR + 64) * 4)

__global__ void __launch_bounds__(256, 2) main_kernel(float* __restrict__ truth) {
    extern __shared__ float sm[];
    float* Qs    = sm;                    // [64][129] -> later V [64][128]
    float* Ks    = Qs + 64 * QS_STR;      // [64][129]
    float* Ws    = Ks + 64 * QS_STR;      // [64][68]
    float* rowKs = Ws + 64 * WS_STR;      // [64]
    float* Vs    = Qs;                    // reuse (stride 128, 16B aligned)

    const int kt = blockIdx.x, qt = blockIdx.y, b = blockIdx.z;
    const int tid = threadIdx.x;
    const int qb = qt * QT, kb = kt * QT;

    if (kt > qt) {   // strictly-upper tile: zero-fill truth and exit
        int r = tid >> 4, c4 = tid & 15;
        float4 z = make_float4(0.f, 0.f, 0.f, 0.f);
#pragma unroll
        for (int rr = 0; rr < 4; rr++) {
            int row = r + rr * 16;
            *(float4*)&truth[((size_t)(b * SS + qb + row)) * SS + kb + c4 * 4] = z;
        }
        return;
    }

    {   // stage Q, K
        const float* Qg = g_Q + ((size_t)b * SS + qb) * DD;
        const float* Kg = g_K + ((size_t)b * SS + kb) * DD;
#pragma unroll
        for (int l = 0; l < 32; l++) {
            int idx = tid + l * 256;
            int r = idx >> 7, dd = idx & 127;
            Qs[r * QS_STR + dd] = Qg[idx];
            Ks[r * QS_STR + dd] = Kg[idx];
        }
        if (tid < 64) rowKs[tid] = g_rowK[b * SS + kb + tid];
    }
    __syncthreads();

    const int ty = tid >> 4, tx = tid & 15;
    const float* qp = Qs + (ty * 4) * QS_STR;
    const float* kp = Ks + (tx * 4) * QS_STR;

    float acc[4][4];
#pragma unroll
    for (int a = 0; a < 4; a++)
#pragma unroll
        for (int j = 0; j < 4; j++) acc[a][j] = 0.0f;

#pragma unroll 8
    for (int dd = 0; dd < DD; dd++) {
        float qv[4], kv[4], cv[4];
#pragma unroll
        for (int a = 0; a < 4; a++) qv[a] = qp[a * QS_STR + dd];
#pragma unroll
        for (int j = 0; j < 4; j++) { kv[j] = kp[j * QS_STR + dd]; cv[j] = 1.0f - kv[j]; }
#pragma unroll
        for (int a = 0; a < 4; a++)
#pragma unroll
            for (int j = 0; j < 4; j++)
                if (qv[a] <= kv[j]) acc[a][j] += cv[j];
    }

    // truth values + softmax weights
    float wv_[4][4];
#pragma unroll
    for (int a = 0; a < 4; a++) {
        int qg = qb + ty * 4 + a;
#pragma unroll
        for (int j = 0; j < 4; j++) {
            int kg = kb + tx * 4 + j;
            float t = (rowKs[tx * 4 + j] + acc[a][j]) * (1.0f / DD);
            bool valid = (kg <= qg);
            t = valid ? t : 0.0f;
            Ws[(ty * 4 + a) * WS_STR + tx * 4 + j] = t;
            wv_[a][j] = valid ? __expf(10.0f * t) : 0.0f;
        }
    }
    __syncthreads();

    {   // coalesced truth store
        int r = tid >> 4, c4 = tid & 15;
#pragma unroll
        for (int rr = 0; rr < 4; rr++) {
            int row = r + rr * 16;
            float4 tv = *(float4*)&Ws[row * WS_STR + c4 * 4];
            *(float4*)&truth[((size_t)(b * SS + qb + row)) * SS + kb + c4 * 4] = tv;
        }
    }
    __syncthreads();   // Qs (and truth values in Ws) fully consumed

    {   // stage V into the Q buffer (stride 128)
        const float* Vg = g_V + ((size_t)b * SS + kb) * DD;
#pragma unroll
        for (int l = 0; l < 32; l++) {
            int idx = tid + l * 256;
            Vs[idx] = Vg[idx];
        }
    }

    // overwrite Ws with weights
#pragma unroll
    for (int a = 0; a < 4; a++)
#pragma unroll
        for (int j = 0; j < 4; j++)
            Ws[(ty * 4 + a) * WS_STR + tx * 4 + j] = wv_[a][j];

    // partial Z per q-row: reduce across the 16 tx lanes (lane bits 0-3)
    const int slot = (b * NT + qt) * NT + kt;
    {
        float rs[4];
#pragma unroll
        for (int a = 0; a < 4; a++)
            rs[a] = wv_[a][0] + wv_[a][1] + wv_[a][2] + wv_[a][3];
#pragma unroll
        for (int a = 0; a < 4; a++) {
            rs[a] += __shfl_xor_sync(0xffffffffu, rs[a], 8);
            rs[a] += __shfl_xor_sync(0xffffffffu, rs[a], 4);
            rs[a] += __shfl_xor_sync(0xffffffffu, rs[a], 2);
            rs[a] += __shfl_xor_sync(0xffffffffu, rs[a], 1);
        }
        if (tx == 0) {
#pragma unroll
            for (int a = 0; a < 4; a++)
                g_partZ[(size_t)slot * QT + ty * 4 + a] = rs[a];
        }
    }
    __syncthreads();

    // partial out = W(64x64) @ V(64x128); thread tile 4q x 8d
    float oacc[4][8];
#pragma unroll
    for (int a = 0; a < 4; a++)
#pragma unroll
        for (int c = 0; c < 8; c++) oacc[a][c] = 0.0f;

#pragma unroll 4
    for (int kk = 0; kk < QT; kk++) {
        float wr[4];
#pragma unroll
        for (int a = 0; a < 4; a++) wr[a] = Ws[(ty * 4 + a) * WS_STR + kk];
        const float4 va = *(const float4*)&Vs[kk * DD + tx * 8];
        const float4 vb = *(const float4*)&Vs[kk * DD + tx * 8 + 4];
#pragma unroll
        for (int a = 0; a < 4; a++) {
            oacc[a][0] += wr[a] * va.x;  oacc[a][1] += wr[a] * va.y;
            oacc[a][2] += wr[a] * va.z;  oacc[a][3] += wr[a] * va.w;
            oacc[a][4] += wr[a] * vb.x;  oacc[a][5] += wr[a] * vb.y;
            oacc[a][6] += wr[a] * vb.z;  oacc[a][7] += wr[a] * vb.w;
        }
    }
    float* po = g_partOut + (size_t)slot * QT * DD;
#pragma unroll
    for (int a = 0; a < 4; a++) {
        *(float4*)&po[(ty * 4 + a) * DD + tx * 8] =
            make_float4(oacc[a][0], oacc[a][1], oacc[a][2], oacc[a][3]);
        *(float4*)&po[(ty * 4 + a) * DD + tx * 8 + 4] =
            make_float4(oacc[a][4], oacc[a][5], oacc[a][6], oacc[a][7]);
    }
}

// ---------------- kernel 4: combine partials + masked tail, normalize ----------------
// grid (qt=16, b=2, ds=4), 256 threads. Each thread: 1 row x 8 cols; kt walked in pairs.
__global__ void combine_kernel(float* __restrict__ out) {
    const int qt = blockIdx.x, b = blockIdx.y, ds = blockIdx.z;
    const int tid = threadIdx.x;
    const int row = tid >> 2;                 // 0..63
    const int cs  = ds * 32 + (tid & 3) * 8;  // col offset

    float acc[8];
#pragma unroll
    for (int c = 0; c < 8; c++) acc[c] = 0.0f;
    float z = 0.0f;

    const size_t rowoff = (size_t)row * DD + cs;
    int kt = 0;
    for (; kt + 1 <= qt; kt += 2) {
        int slot0 = (b * NT + qt) * NT + kt;
        int slot1 = slot0 + 1;
        const float* p0 = g_partOut + (size_t)slot0 * QT * DD + rowoff;
        const float* p1 = g_partOut + (size_t)slot1 * QT * DD + rowoff;
        const float4 a0 = *(const float4*)p0;
        const float4 a1 = *(const float4*)(p0 + 4);
        const float4 b0 = *(const float4*)p1;
        const float4 b1 = *(const float4*)(p1 + 4);
        float z0 = g_partZ[(size_t)slot0 * QT + row];
        float z1 = g_partZ[(size_t)slot1 * QT + row];
        acc[0] += a0.x + b0.x; acc[1] += a0.y + b0.y;
        acc[2] += a0.z + b0.z; acc[3] += a0.w + b0.w;
        acc[4] += a1.x + b1.x; acc[5] += a1.y + b1.y;
        acc[6] += a1.z + b1.z; acc[7] += a1.w + b1.w;
        z += z0 + z1;
    }
    if (kt <= qt) {
        int slot = (b * NT + qt) * NT + kt;
        const float* p0 = g_partOut + (size_t)slot * QT * DD + rowoff;
        const float4 a0 = *(const float4*)p0;
        const float4 a1 = *(const float4*)(p0 + 4);
        acc[0] += a0.x; acc[1] += a0.y; acc[2] += a0.z; acc[3] += a0.w;
        acc[4] += a1.x; acc[5] += a1.y; acc[6] += a1.z; acc[7] += a1.w;
        z += g_partZ[(size_t)slot * QT + row];
    }

    const int qg = qt * QT + row;
    const float Z = z + (float)(SS - 1 - qg);
    const float r = 1.0f / Z;
    const float* sv = g_suffV + ((size_t)b * SS + qg) * DD + cs;
    const float4 s0 = *(const float4*)sv;
    const float4 s1 = *(const float4*)(sv + 4);
    float4 o0, o1;
    o0.x = (acc[0] + s0.x) * r;  o0.y = (acc[1] + s0.y) * r;
    o0.z = (acc[2] + s0.z) * r;  o0.w = (acc[3] + s0.w) * r;
    o1.x = (acc[4] + s1.x) * r;  o1.y = (acc[5] + s1.y) * r;
    o1.z = (acc[6] + s1.z) * r;  o1.w = (acc[7] + s1.w) * r;
    float* op = out + ((size_t)b * SS + qg) * DD + cs;
    *(float4*)op       = o0;
    *(float4*)(op + 4) = o1;
}

// ---------------- launch ----------------
extern "C" void kernel_launch(void* const* d_in, const int* in_sizes, int n_in,
                              void* d_out, int out_size) {
    const float* x  = (const float*)d_in[0];
    const float* wq = (const float*)d_in[1];
    const float* bq = (const float*)d_in[2];
    const float* wk = (const float*)d_in[3];
    const float* bk = (const float*)d_in[4];
    const float* wv = (const float*)d_in[5];
    const float* bv = (const float*)d_in[6];
    float* out = (float*)d_out;
    float* truth = out + (size_t)BB * SS * DD;   // output first, then attention_truth

    cudaFuncSetAttribute(main_kernel, cudaFuncAttributeMaxDynamicSharedMemorySize, SMEM_MAIN);

    qkv_kernel<<<dim3(32, 3), 256>>>(x, wq, bq, wk, bk, wv, bv);
    suffix_kernel<<<BB * NT, 128>>>();
    main_kernel<<<dim3(NT, NT, BB), 256, SMEM_MAIN>>>(truth);
    combine_kernel<<<dim3(NT, BB, 4), 256>>>(out);
}